// round 4
// baseline (speedup 1.0000x reference)
#include <cuda_runtime.h>
#include <cstddef>

// ---------------------------------------------------------------------------
// Decoder_73495480369571: 6-layer dense 3D transposed-conv decoder, fp32.
// conv_transpose (transpose_kernel=False, SAME, k=3):
//   stride 1: SAME cross-correlation pad 1.
//   stride 2: per dim: out[2m] = in[m-1]*w[0] + in[m]*w[2]; out[2m+1] = in[m]*w[1]
// Weights DHWIO: w[kz][ky][kx][ci][co] (co contiguous). Acts NCDHW (N=1).
//
// R3: packed fma.rn.f32x2 (FFMA2) — consecutive-co pairs share one fma-pipe
// slot; weight float2/float4 loads are already the packed operand.
// ---------------------------------------------------------------------------

typedef unsigned long long u64;

__device__ __forceinline__ u64 fma2(u64 a, u64 b, u64 c) {
    u64 d;
    asm("fma.rn.f32x2 %0, %1, %2, %3;" : "=l"(d) : "l"(a), "l"(b), "l"(c));
    return d;
}
__device__ __forceinline__ u64 bcast2(float x) {
    u64 d;
    asm("mov.b64 %0, {%1, %2};" : "=l"(d) : "f"(x), "f"(x));
    return d;
}
__device__ __forceinline__ void unpk(u64 v, float& lo, float& hi) {
    asm("mov.b64 {%0, %1}, %2;" : "=f"(lo), "=f"(hi) : "l"(v));
}

template <int PAIRS>
__device__ __forceinline__ void ldwp(const float* __restrict__ p, u64* v) {
    if constexpr (PAIRS == 2) {
        ulonglong2 t = __ldg((const ulonglong2*)p);
        v[0] = t.x; v[1] = t.y;
    } else {
        v[0] = __ldg((const u64*)p);
    }
}

// Scratch (__device__ globals; allocation-free rule).
__device__ float g_h1[512 * 512];
__device__ float g_h2[256 * 512];
__device__ float g_h3[128 * 4096];
__device__ float g_h4[64 * 4096];
__device__ float g_h5[32 * 32768];
__device__ float g_p1[8  * 512 * 512];
__device__ float g_p2[16 * 256 * 512];
__device__ float g_p3[8  * 128 * 4096];
__device__ float g_p4[16 * 64 * 4096];
__device__ float g_p5[4  * 32 * 32768];

// ---------------------------------------------------------------------------
// Stride-2 transposed conv, packed co-pairs. Thread: 2*PAIRS consecutive co,
// one (z,y), full output x-row in packed registers. blockIdx.z = split-K.
// ---------------------------------------------------------------------------
template <int DXIN, int PAIRS>
__global__ void ct_s2p(const float* __restrict__ in, const float* __restrict__ w,
                       float* __restrict__ out, int Ci, int Co, int ciChunk)
{
    constexpr int DO = 2 * DXIN;
    const int co = (blockIdx.y * blockDim.x + threadIdx.x) * (2 * PAIRS);
    const int z  = blockIdx.x / DO;
    const int y  = blockIdx.x % DO;
    const int ci0 = blockIdx.z * ciChunk;
    out += (size_t)blockIdx.z * Co * (DO * DO * DO);

    u64 acc[PAIRS][DO];
#pragma unroll
    for (int p = 0; p < PAIRS; p++)
#pragma unroll
        for (int i = 0; i < DO; i++) acc[p][i] = 0ull;

    int zk[2], zi[2], nz = 0;
#pragma unroll
    for (int k = 0; k < 3; k++)
        if (((z + k) & 1) == 0) {
            int t = (z + k - 2) / 2;
            if (t >= 0 && t < DXIN) { zk[nz] = k; zi[nz] = t; nz++; }
        }
    int yk[2], yi[2], ny = 0;
#pragma unroll
    for (int k = 0; k < 3; k++)
        if (((y + k) & 1) == 0) {
            int t = (y + k - 2) / 2;
            if (t >= 0 && t < DXIN) { yk[ny] = k; yi[ny] = t; ny++; }
        }

    const int CC = Ci * Co;
    for (int ci = ci0; ci < ci0 + ciChunk; ci++) {
        const float* inc = in + (size_t)ci * (DXIN * DXIN * DXIN);
        for (int a = 0; a < nz; a++) {
            for (int b = 0; b < ny; b++) {
                const float* row = inc + (zi[a] * DXIN + yi[b]) * DXIN;
                u64 rp[DXIN];
#pragma unroll
                for (int q = 0; q < DXIN / 4; q++) {
                    float4 t = __ldg((const float4*)row + q);
                    rp[4 * q + 0] = bcast2(t.x); rp[4 * q + 1] = bcast2(t.y);
                    rp[4 * q + 2] = bcast2(t.z); rp[4 * q + 3] = bcast2(t.w);
                }
                const float* wp = w + (size_t)((zk[a] * 3 + yk[b]) * 3) * CC
                                    + (size_t)ci * Co + co;
                u64 w0[PAIRS], w1[PAIRS], w2[PAIRS];
                ldwp<PAIRS>(wp, w0); ldwp<PAIRS>(wp + CC, w1); ldwp<PAIRS>(wp + 2 * CC, w2);
#pragma unroll
                for (int p = 0; p < PAIRS; p++) {
#pragma unroll
                    for (int m = 1; m < DXIN; m++) acc[p][2 * m]     = fma2(rp[m - 1], w0[p], acc[p][2 * m]);
#pragma unroll
                    for (int m = 0; m < DXIN; m++) acc[p][2 * m + 1] = fma2(rp[m],     w1[p], acc[p][2 * m + 1]);
#pragma unroll
                    for (int m = 0; m < DXIN; m++) acc[p][2 * m]     = fma2(rp[m],     w2[p], acc[p][2 * m]);
                }
            }
        }
    }

#pragma unroll
    for (int p = 0; p < PAIRS; p++) {
        float lo[DO], hi[DO];
#pragma unroll
        for (int xo = 0; xo < DO; xo++) unpk(acc[p][xo], lo[xo], hi[xo]);
        float* opLo = out + (((size_t)(co + 2 * p) * DO + z) * DO + y) * DO;
        float* opHi = opLo + (size_t)DO * DO * DO;
#pragma unroll
        for (int xo = 0; xo < DO; xo++) { opLo[xo] = lo[xo]; opHi[xo] = hi[xo]; }
    }
}

// ---------------------------------------------------------------------------
// Stride-1 SAME conv (3^3, pad 1), packed co-pairs.
// ---------------------------------------------------------------------------
template <int DX, int PAIRS>
__global__ void ct_s1p(const float* __restrict__ in, const float* __restrict__ w,
                       float* __restrict__ out, int Ci, int Co, int ciChunk)
{
    const int co = (blockIdx.y * blockDim.x + threadIdx.x) * (2 * PAIRS);
    const int z  = blockIdx.x / DX;
    const int y  = blockIdx.x % DX;
    const int ci0 = blockIdx.z * ciChunk;
    out += (size_t)blockIdx.z * Co * (DX * DX * DX);

    u64 acc[PAIRS][DX];
#pragma unroll
    for (int p = 0; p < PAIRS; p++)
#pragma unroll
        for (int i = 0; i < DX; i++) acc[p][i] = 0ull;

    const int CC = Ci * Co;
    for (int ci = ci0; ci < ci0 + ciChunk; ci++) {
        const float* inc = in + (size_t)ci * (DX * DX * DX);
#pragma unroll
        for (int kz = 0; kz < 3; kz++) {
            const int ziv = z + kz - 1;
            if (ziv < 0 || ziv >= DX) continue;
#pragma unroll
            for (int ky = 0; ky < 3; ky++) {
                const int yiv = y + ky - 1;
                if (yiv < 0 || yiv >= DX) continue;
                const float* row = inc + (ziv * DX + yiv) * DX;
                u64 rp[DX];
#pragma unroll
                for (int q = 0; q < DX / 4; q++) {
                    float4 t = __ldg((const float4*)row + q);
                    rp[4 * q + 0] = bcast2(t.x); rp[4 * q + 1] = bcast2(t.y);
                    rp[4 * q + 2] = bcast2(t.z); rp[4 * q + 3] = bcast2(t.w);
                }
                const float* wp = w + (size_t)((kz * 3 + ky) * 3) * CC
                                    + (size_t)ci * Co + co;
                u64 w0[PAIRS], w1[PAIRS], w2[PAIRS];
                ldwp<PAIRS>(wp, w0); ldwp<PAIRS>(wp + CC, w1); ldwp<PAIRS>(wp + 2 * CC, w2);
#pragma unroll
                for (int p = 0; p < PAIRS; p++) {
#pragma unroll
                    for (int x = 1; x < DX; x++)     acc[p][x] = fma2(rp[x - 1], w0[p], acc[p][x]);
#pragma unroll
                    for (int x = 0; x < DX; x++)     acc[p][x] = fma2(rp[x],     w1[p], acc[p][x]);
#pragma unroll
                    for (int x = 0; x < DX - 1; x++) acc[p][x] = fma2(rp[x + 1], w2[p], acc[p][x]);
                }
            }
        }
    }

#pragma unroll
    for (int p = 0; p < PAIRS; p++) {
        float lo[DX], hi[DX];
#pragma unroll
        for (int x = 0; x < DX; x++) unpk(acc[p][x], lo[x], hi[x]);
        float* opLo = out + (((size_t)(co + 2 * p) * DX + z) * DX + y) * DX;
        float* opHi = opLo + (size_t)DX * DX * DX;
#pragma unroll
        for (int x = 0; x < DX; x++) { opLo[x] = lo[x]; opHi[x] = hi[x]; }
    }
}

// ---------------------------------------------------------------------------
// L5 scalar stride-2 (small layer; packed accs would spill).
// ---------------------------------------------------------------------------
template <int DXIN>
__global__ void ct_s2(const float* __restrict__ in, const float* __restrict__ w,
                      float* __restrict__ out, int Ci, int Co, int ciChunk)
{
    constexpr int DO = 2 * DXIN;
    const int co = blockIdx.y * blockDim.x + threadIdx.x;
    const int z  = blockIdx.x / DO;
    const int y  = blockIdx.x % DO;
    const int ci0 = blockIdx.z * ciChunk;
    out += (size_t)blockIdx.z * Co * (DO * DO * DO);

    float acc[DO];
#pragma unroll
    for (int i = 0; i < DO; i++) acc[i] = 0.f;

    int zk[2], zi[2], nz = 0;
#pragma unroll
    for (int k = 0; k < 3; k++)
        if (((z + k) & 1) == 0) {
            int t = (z + k - 2) / 2;
            if (t >= 0 && t < DXIN) { zk[nz] = k; zi[nz] = t; nz++; }
        }
    int yk[2], yi[2], ny = 0;
#pragma unroll
    for (int k = 0; k < 3; k++)
        if (((y + k) & 1) == 0) {
            int t = (y + k - 2) / 2;
            if (t >= 0 && t < DXIN) { yk[ny] = k; yi[ny] = t; ny++; }
        }

    const int CC = Ci * Co;
    for (int ci = ci0; ci < ci0 + ciChunk; ci++) {
        const float* inc = in + (size_t)ci * (DXIN * DXIN * DXIN);
        for (int a = 0; a < nz; a++) {
            for (int b = 0; b < ny; b++) {
                const float* row = inc + (zi[a] * DXIN + yi[b]) * DXIN;
                float rin[DXIN];
#pragma unroll
                for (int q = 0; q < DXIN / 4; q++) {
                    float4 t = __ldg((const float4*)row + q);
                    rin[4 * q + 0] = t.x; rin[4 * q + 1] = t.y;
                    rin[4 * q + 2] = t.z; rin[4 * q + 3] = t.w;
                }
                const float* wp = w + (size_t)((zk[a] * 3 + yk[b]) * 3) * CC
                                    + (size_t)ci * Co + co;
                const float w0 = __ldg(wp);
                const float w1 = __ldg(wp + CC);
                const float w2 = __ldg(wp + 2 * CC);
#pragma unroll
                for (int m = 1; m < DXIN; m++) acc[2 * m]     += rin[m - 1] * w0;
#pragma unroll
                for (int m = 0; m < DXIN; m++) acc[2 * m + 1] += rin[m] * w1;
#pragma unroll
                for (int m = 0; m < DXIN; m++) acc[2 * m]     += rin[m] * w2;
            }
        }
    }

    float* op = out + (((size_t)co * DO + z) * DO + y) * DO;
#pragma unroll
    for (int xo = 0; xo < DO; xo++) op[xo] = acc[xo];
}

// ---------------------------------------------------------------------------
// Final layer: Ci=32 -> Co=1, D=32, stride 1, no ReLU.
// ---------------------------------------------------------------------------
__global__ void ct_final(const float* __restrict__ in, const float* __restrict__ w,
                         float* __restrict__ out)
{
    constexpr int Ci = 32, D = 32;
    __shared__ float ws[27 * Ci];
    for (int i = threadIdx.x; i < 27 * Ci; i += blockDim.x) ws[i] = w[i];
    __syncthreads();

    const int idx = blockIdx.x * blockDim.x + threadIdx.x;
    const int x = idx & 31;
    const int y = (idx >> 5) & 31;
    const int z = idx >> 10;

    float acc = 0.f;
#pragma unroll
    for (int kz = 0; kz < 3; kz++) {
        const int zi = z + kz - 1;
        if (zi < 0 || zi >= D) continue;
#pragma unroll
        for (int ky = 0; ky < 3; ky++) {
            const int yi = y + ky - 1;
            if (yi < 0 || yi >= D) continue;
#pragma unroll
            for (int kx = 0; kx < 3; kx++) {
                const int xi = x + kx - 1;
                if (xi < 0 || xi >= D) continue;
                const float* ip = in + (zi * D + yi) * D + xi;
                const float* wk = ws + ((kz * 3 + ky) * 3 + kx) * Ci;
#pragma unroll 8
                for (int ci = 0; ci < Ci; ci++)
                    acc += __ldg(ip + (size_t)ci * D * D * D) * wk[ci];
            }
        }
    }
    out[idx] = acc;
}

// Fixed-order split-K reduction + ReLU, float4-vectorized (deterministic).
__global__ void reduce_relu4(const float4* __restrict__ part, float4* __restrict__ out,
                             int n4, int S)
{
    const int i = blockIdx.x * blockDim.x + threadIdx.x;
    if (i >= n4) return;
    float4 v = make_float4(0.f, 0.f, 0.f, 0.f);
    for (int s = 0; s < S; s++) {
        float4 p = part[(size_t)s * n4 + i];
        v.x += p.x; v.y += p.y; v.z += p.z; v.w += p.w;
    }
    v.x = fmaxf(v.x, 0.f); v.y = fmaxf(v.y, 0.f);
    v.z = fmaxf(v.z, 0.f); v.w = fmaxf(v.w, 0.f);
    out[i] = v;
}

// ---------------------------------------------------------------------------
extern "C" void kernel_launch(void* const* d_in, const int* in_sizes, int n_in,
                              void* d_out, int out_size)
{
    (void)in_sizes; (void)n_in; (void)out_size;
    const float* x  = (const float*)d_in[0];
    const float* w1 = (const float*)d_in[1];
    const float* w2 = (const float*)d_in[2];
    const float* w3 = (const float*)d_in[3];
    const float* w4 = (const float*)d_in[4];
    const float* w5 = (const float*)d_in[5];
    const float* w6 = (const float*)d_in[6];
    float* out = (float*)d_out;

    float *h1, *h2, *h3, *h4, *h5, *p1, *p2, *p3, *p4, *p5;
    cudaGetSymbolAddress((void**)&h1, g_h1);
    cudaGetSymbolAddress((void**)&h2, g_h2);
    cudaGetSymbolAddress((void**)&h3, g_h3);
    cudaGetSymbolAddress((void**)&h4, g_h4);
    cudaGetSymbolAddress((void**)&h5, g_h5);
    cudaGetSymbolAddress((void**)&p1, g_p1);
    cudaGetSymbolAddress((void**)&p2, g_p2);
    cudaGetSymbolAddress((void**)&p3, g_p3);
    cudaGetSymbolAddress((void**)&p4, g_p4);
    cudaGetSymbolAddress((void**)&p5, g_p5);

    // L1: 1024->512, 4^3->8^3, s2. 128 co-quads, split 8.
    ct_s2p<4, 2><<<dim3(64, 1, 8), 128>>>(x, w1, p1, 1024, 512, 128);
    reduce_relu4<<<(512 * 512 / 4 + 255) / 256, 256>>>((const float4*)p1, (float4*)h1,
                                                       512 * 512 / 4, 8);

    // L2: 512->256, 8^3, s1. 64 co-quads, split 16.
    ct_s1p<8, 2><<<dim3(64, 1, 16), 64>>>(h1, w2, p2, 512, 256, 32);
    reduce_relu4<<<(256 * 512 / 4 + 255) / 256, 256>>>((const float4*)p2, (float4*)h2,
                                                       256 * 512 / 4, 16);

    // L3: 256->128, 8^3->16^3, s2. 64 co-pairs, split 8.
    ct_s2p<8, 1><<<dim3(256, 1, 8), 64>>>(h2, w3, p3, 256, 128, 32);
    reduce_relu4<<<(128 * 4096 / 4 + 255) / 256, 256>>>((const float4*)p3, (float4*)h3,
                                                        128 * 4096 / 4, 8);

    // L4: 128->64, 16^3, s1. 32 co-pairs, split 16.
    ct_s1p<16, 1><<<dim3(256, 1, 16), 32>>>(h3, w4, p4, 128, 64, 8);
    reduce_relu4<<<(64 * 4096 / 4 + 255) / 256, 256>>>((const float4*)p4, (float4*)h4,
                                                       64 * 4096 / 4, 16);

    // L5: 64->32, 16^3->32^3, s2 scalar, split 4.
    ct_s2<16><<<dim3(1024, 1, 4), 32>>>(h4, w5, p5, 64, 32, 16);
    reduce_relu4<<<(32 * 32768 / 4 + 255) / 256, 256>>>((const float4*)p5, (float4*)h5,
                                                        32 * 32768 / 4, 4);

    // L6: 32->1, 32^3, s1, no ReLU.
    ct_final<<<256, 128>>>(h5, w6, out);
}

// round 5
// speedup vs baseline: 1.1521x; 1.1521x over previous
#include <cuda_runtime.h>
#include <cstddef>

// ---------------------------------------------------------------------------
// Decoder_73495480369571: 6-layer dense 3D transposed-conv decoder, fp32.
// conv_transpose (transpose_kernel=False, SAME, k=3):
//   stride 1: SAME cross-correlation pad 1.
//   stride 2: per dim: out[2m] = in[m-1]*w[0] + in[m]*w[2]; out[2m+1] = in[m]*w[1]
// Weights DHWIO: w[kz][ky][kx][ci][co] (co contiguous). Acts NCDHW (N=1).
//
// R4: f32x2 packed math (R3) + restored occupancy (4096-8192 warps/layer via
// deeper split-K) + ci-loop unroll for MLP.
// ---------------------------------------------------------------------------

typedef unsigned long long u64;

__device__ __forceinline__ u64 fma2(u64 a, u64 b, u64 c) {
    u64 d;
    asm("fma.rn.f32x2 %0, %1, %2, %3;" : "=l"(d) : "l"(a), "l"(b), "l"(c));
    return d;
}
__device__ __forceinline__ u64 bcast2(float x) {
    u64 d;
    asm("mov.b64 %0, {%1, %2};" : "=l"(d) : "f"(x), "f"(x));
    return d;
}
__device__ __forceinline__ void unpk(u64 v, float& lo, float& hi) {
    asm("mov.b64 {%0, %1}, %2;" : "=f"(lo), "=f"(hi) : "l"(v));
}

template <int PAIRS>
__device__ __forceinline__ void ldwp(const float* __restrict__ p, u64* v) {
    if constexpr (PAIRS == 2) {
        ulonglong2 t = __ldg((const ulonglong2*)p);
        v[0] = t.x; v[1] = t.y;
    } else {
        v[0] = __ldg((const u64*)p);
    }
}

// Scratch (__device__ globals; allocation-free rule).
__device__ float g_h1[512 * 512];
__device__ float g_h2[256 * 512];
__device__ float g_h3[128 * 4096];
__device__ float g_h4[64 * 4096];
__device__ float g_h5[32 * 32768];
__device__ float g_p1[16 * 512 * 512];
__device__ float g_p2[32 * 256 * 512];
__device__ float g_p3[16 * 128 * 4096];
__device__ float g_p4[32 * 64 * 4096];
__device__ float g_p5[8  * 32 * 32768];

// ---------------------------------------------------------------------------
// Stride-2 transposed conv, packed co-pairs. Thread: 2*PAIRS consecutive co,
// one (z,y), full output x-row in packed registers. blockIdx.z = split-K.
// ---------------------------------------------------------------------------
template <int DXIN, int PAIRS>
__global__ void ct_s2p(const float* __restrict__ in, const float* __restrict__ w,
                       float* __restrict__ out, int Ci, int Co, int ciChunk)
{
    constexpr int DO = 2 * DXIN;
    const int co = (blockIdx.y * blockDim.x + threadIdx.x) * (2 * PAIRS);
    const int z  = blockIdx.x / DO;
    const int y  = blockIdx.x % DO;
    const int ci0 = blockIdx.z * ciChunk;
    out += (size_t)blockIdx.z * Co * (DO * DO * DO);

    u64 acc[PAIRS][DO];
#pragma unroll
    for (int p = 0; p < PAIRS; p++)
#pragma unroll
        for (int i = 0; i < DO; i++) acc[p][i] = 0ull;

    int zk[2], zi[2], nz = 0;
#pragma unroll
    for (int k = 0; k < 3; k++)
        if (((z + k) & 1) == 0) {
            int t = (z + k - 2) / 2;
            if (t >= 0 && t < DXIN) { zk[nz] = k; zi[nz] = t; nz++; }
        }
    int yk[2], yi[2], ny = 0;
#pragma unroll
    for (int k = 0; k < 3; k++)
        if (((y + k) & 1) == 0) {
            int t = (y + k - 2) / 2;
            if (t >= 0 && t < DXIN) { yk[ny] = k; yi[ny] = t; ny++; }
        }

    const int CC = Ci * Co;
#pragma unroll 2
    for (int ci = ci0; ci < ci0 + ciChunk; ci++) {
        const float* inc = in + (size_t)ci * (DXIN * DXIN * DXIN);
        for (int a = 0; a < nz; a++) {
            for (int b = 0; b < ny; b++) {
                const float* row = inc + (zi[a] * DXIN + yi[b]) * DXIN;
                u64 rp[DXIN];
#pragma unroll
                for (int q = 0; q < DXIN / 4; q++) {
                    float4 t = __ldg((const float4*)row + q);
                    rp[4 * q + 0] = bcast2(t.x); rp[4 * q + 1] = bcast2(t.y);
                    rp[4 * q + 2] = bcast2(t.z); rp[4 * q + 3] = bcast2(t.w);
                }
                const float* wp = w + (size_t)((zk[a] * 3 + yk[b]) * 3) * CC
                                    + (size_t)ci * Co + co;
                u64 w0[PAIRS], w1[PAIRS], w2[PAIRS];
                ldwp<PAIRS>(wp, w0); ldwp<PAIRS>(wp + CC, w1); ldwp<PAIRS>(wp + 2 * CC, w2);
#pragma unroll
                for (int p = 0; p < PAIRS; p++) {
#pragma unroll
                    for (int m = 1; m < DXIN; m++) acc[p][2 * m]     = fma2(rp[m - 1], w0[p], acc[p][2 * m]);
#pragma unroll
                    for (int m = 0; m < DXIN; m++) acc[p][2 * m + 1] = fma2(rp[m],     w1[p], acc[p][2 * m + 1]);
#pragma unroll
                    for (int m = 0; m < DXIN; m++) acc[p][2 * m]     = fma2(rp[m],     w2[p], acc[p][2 * m]);
                }
            }
        }
    }

#pragma unroll
    for (int p = 0; p < PAIRS; p++) {
        float lo[DO], hi[DO];
#pragma unroll
        for (int xo = 0; xo < DO; xo++) unpk(acc[p][xo], lo[xo], hi[xo]);
        float* opLo = out + (((size_t)(co + 2 * p) * DO + z) * DO + y) * DO;
        float* opHi = opLo + (size_t)DO * DO * DO;
#pragma unroll
        for (int xo = 0; xo < DO; xo++) { opLo[xo] = lo[xo]; opHi[xo] = hi[xo]; }
    }
}

// ---------------------------------------------------------------------------
// Stride-1 SAME conv (3^3, pad 1), packed co-pairs.
// ---------------------------------------------------------------------------
template <int DX, int PAIRS>
__global__ void ct_s1p(const float* __restrict__ in, const float* __restrict__ w,
                       float* __restrict__ out, int Ci, int Co, int ciChunk)
{
    const int co = (blockIdx.y * blockDim.x + threadIdx.x) * (2 * PAIRS);
    const int z  = blockIdx.x / DX;
    const int y  = blockIdx.x % DX;
    const int ci0 = blockIdx.z * ciChunk;
    out += (size_t)blockIdx.z * Co * (DX * DX * DX);

    u64 acc[PAIRS][DX];
#pragma unroll
    for (int p = 0; p < PAIRS; p++)
#pragma unroll
        for (int i = 0; i < DX; i++) acc[p][i] = 0ull;

    const int CC = Ci * Co;
#pragma unroll 2
    for (int ci = ci0; ci < ci0 + ciChunk; ci++) {
        const float* inc = in + (size_t)ci * (DX * DX * DX);
#pragma unroll
        for (int kz = 0; kz < 3; kz++) {
            const int ziv = z + kz - 1;
            if (ziv < 0 || ziv >= DX) continue;
#pragma unroll
            for (int ky = 0; ky < 3; ky++) {
                const int yiv = y + ky - 1;
                if (yiv < 0 || yiv >= DX) continue;
                const float* row = inc + (ziv * DX + yiv) * DX;
                u64 rp[DX];
#pragma unroll
                for (int q = 0; q < DX / 4; q++) {
                    float4 t = __ldg((const float4*)row + q);
                    rp[4 * q + 0] = bcast2(t.x); rp[4 * q + 1] = bcast2(t.y);
                    rp[4 * q + 2] = bcast2(t.z); rp[4 * q + 3] = bcast2(t.w);
                }
                const float* wp = w + (size_t)((kz * 3 + ky) * 3) * CC
                                    + (size_t)ci * Co + co;
                u64 w0[PAIRS], w1[PAIRS], w2[PAIRS];
                ldwp<PAIRS>(wp, w0); ldwp<PAIRS>(wp + CC, w1); ldwp<PAIRS>(wp + 2 * CC, w2);
#pragma unroll
                for (int p = 0; p < PAIRS; p++) {
#pragma unroll
                    for (int x = 1; x < DX; x++)     acc[p][x] = fma2(rp[x - 1], w0[p], acc[p][x]);
#pragma unroll
                    for (int x = 0; x < DX; x++)     acc[p][x] = fma2(rp[x],     w1[p], acc[p][x]);
#pragma unroll
                    for (int x = 0; x < DX - 1; x++) acc[p][x] = fma2(rp[x + 1], w2[p], acc[p][x]);
                }
            }
        }
    }

#pragma unroll
    for (int p = 0; p < PAIRS; p++) {
        float lo[DX], hi[DX];
#pragma unroll
        for (int x = 0; x < DX; x++) unpk(acc[p][x], lo[x], hi[x]);
        float* opLo = out + (((size_t)(co + 2 * p) * DX + z) * DX + y) * DX;
        float* opHi = opLo + (size_t)DX * DX * DX;
#pragma unroll
        for (int x = 0; x < DX; x++) { opLo[x] = lo[x]; opHi[x] = hi[x]; }
    }
}

// ---------------------------------------------------------------------------
// L5 scalar stride-2 (Co=32; packed accs would spill).
// ---------------------------------------------------------------------------
template <int DXIN>
__global__ void ct_s2(const float* __restrict__ in, const float* __restrict__ w,
                      float* __restrict__ out, int Ci, int Co, int ciChunk)
{
    constexpr int DO = 2 * DXIN;
    const int co = blockIdx.y * blockDim.x + threadIdx.x;
    const int z  = blockIdx.x / DO;
    const int y  = blockIdx.x % DO;
    const int ci0 = blockIdx.z * ciChunk;
    out += (size_t)blockIdx.z * Co * (DO * DO * DO);

    float acc[DO];
#pragma unroll
    for (int i = 0; i < DO; i++) acc[i] = 0.f;

    int zk[2], zi[2], nz = 0;
#pragma unroll
    for (int k = 0; k < 3; k++)
        if (((z + k) & 1) == 0) {
            int t = (z + k - 2) / 2;
            if (t >= 0 && t < DXIN) { zk[nz] = k; zi[nz] = t; nz++; }
        }
    int yk[2], yi[2], ny = 0;
#pragma unroll
    for (int k = 0; k < 3; k++)
        if (((y + k) & 1) == 0) {
            int t = (y + k - 2) / 2;
            if (t >= 0 && t < DXIN) { yk[ny] = k; yi[ny] = t; ny++; }
        }

    const int CC = Ci * Co;
#pragma unroll 2
    for (int ci = ci0; ci < ci0 + ciChunk; ci++) {
        const float* inc = in + (size_t)ci * (DXIN * DXIN * DXIN);
        for (int a = 0; a < nz; a++) {
            for (int b = 0; b < ny; b++) {
                const float* row = inc + (zi[a] * DXIN + yi[b]) * DXIN;
                float rin[DXIN];
#pragma unroll
                for (int q = 0; q < DXIN / 4; q++) {
                    float4 t = __ldg((const float4*)row + q);
                    rin[4 * q + 0] = t.x; rin[4 * q + 1] = t.y;
                    rin[4 * q + 2] = t.z; rin[4 * q + 3] = t.w;
                }
                const float* wp = w + (size_t)((zk[a] * 3 + yk[b]) * 3) * CC
                                    + (size_t)ci * Co + co;
                const float w0 = __ldg(wp);
                const float w1 = __ldg(wp + CC);
                const float w2 = __ldg(wp + 2 * CC);
#pragma unroll
                for (int m = 1; m < DXIN; m++) acc[2 * m]     += rin[m - 1] * w0;
#pragma unroll
                for (int m = 0; m < DXIN; m++) acc[2 * m + 1] += rin[m] * w1;
#pragma unroll
                for (int m = 0; m < DXIN; m++) acc[2 * m]     += rin[m] * w2;
            }
        }
    }

    float* op = out + (((size_t)co * DO + z) * DO + y) * DO;
#pragma unroll
    for (int xo = 0; xo < DO; xo++) op[xo] = acc[xo];
}

// ---------------------------------------------------------------------------
// Final layer: Ci=32 -> Co=1, D=32, stride 1, no ReLU.
// ---------------------------------------------------------------------------
__global__ void ct_final(const float* __restrict__ in, const float* __restrict__ w,
                         float* __restrict__ out)
{
    constexpr int Ci = 32, D = 32;
    __shared__ float ws[27 * Ci];
    for (int i = threadIdx.x; i < 27 * Ci; i += blockDim.x) ws[i] = w[i];
    __syncthreads();

    const int idx = blockIdx.x * blockDim.x + threadIdx.x;
    const int x = idx & 31;
    const int y = (idx >> 5) & 31;
    const int z = idx >> 10;

    float acc = 0.f;
#pragma unroll
    for (int kz = 0; kz < 3; kz++) {
        const int zi = z + kz - 1;
        if (zi < 0 || zi >= D) continue;
#pragma unroll
        for (int ky = 0; ky < 3; ky++) {
            const int yi = y + ky - 1;
            if (yi < 0 || yi >= D) continue;
#pragma unroll
            for (int kx = 0; kx < 3; kx++) {
                const int xi = x + kx - 1;
                if (xi < 0 || xi >= D) continue;
                const float* ip = in + (zi * D + yi) * D + xi;
                const float* wk = ws + ((kz * 3 + ky) * 3 + kx) * Ci;
#pragma unroll 8
                for (int ci = 0; ci < Ci; ci++)
                    acc += __ldg(ip + (size_t)ci * D * D * D) * wk[ci];
            }
        }
    }
    out[idx] = acc;
}

// Fixed-order split-K reduction + ReLU, float4-vectorized (deterministic).
__global__ void reduce_relu4(const float4* __restrict__ part, float4* __restrict__ out,
                             int n4, int S)
{
    const int i = blockIdx.x * blockDim.x + threadIdx.x;
    if (i >= n4) return;
    float4 v = make_float4(0.f, 0.f, 0.f, 0.f);
    for (int s = 0; s < S; s++) {
        float4 p = part[(size_t)s * n4 + i];
        v.x += p.x; v.y += p.y; v.z += p.z; v.w += p.w;
    }
    v.x = fmaxf(v.x, 0.f); v.y = fmaxf(v.y, 0.f);
    v.z = fmaxf(v.z, 0.f); v.w = fmaxf(v.w, 0.f);
    out[i] = v;
}

// ---------------------------------------------------------------------------
extern "C" void kernel_launch(void* const* d_in, const int* in_sizes, int n_in,
                              void* d_out, int out_size)
{
    (void)in_sizes; (void)n_in; (void)out_size;
    const float* x  = (const float*)d_in[0];
    const float* w1 = (const float*)d_in[1];
    const float* w2 = (const float*)d_in[2];
    const float* w3 = (const float*)d_in[3];
    const float* w4 = (const float*)d_in[4];
    const float* w5 = (const float*)d_in[5];
    const float* w6 = (const float*)d_in[6];
    float* out = (float*)d_out;

    float *h1, *h2, *h3, *h4, *h5, *p1, *p2, *p3, *p4, *p5;
    cudaGetSymbolAddress((void**)&h1, g_h1);
    cudaGetSymbolAddress((void**)&h2, g_h2);
    cudaGetSymbolAddress((void**)&h3, g_h3);
    cudaGetSymbolAddress((void**)&h4, g_h4);
    cudaGetSymbolAddress((void**)&h5, g_h5);
    cudaGetSymbolAddress((void**)&p1, g_p1);
    cudaGetSymbolAddress((void**)&p2, g_p2);
    cudaGetSymbolAddress((void**)&p3, g_p3);
    cudaGetSymbolAddress((void**)&p4, g_p4);
    cudaGetSymbolAddress((void**)&p5, g_p5);

    // L1: 1024->512, 4^3->8^3, s2. 128 co-quads, split 16 (4096 warps).
    ct_s2p<4, 2><<<dim3(64, 1, 16), 128>>>(x, w1, p1, 1024, 512, 64);
    reduce_relu4<<<(512 * 512 / 4 + 255) / 256, 256>>>((const float4*)p1, (float4*)h1,
                                                       512 * 512 / 4, 16);

    // L2: 512->256, 8^3, s1. 64 co-quads, split 32 (4096 warps).
    ct_s1p<8, 2><<<dim3(64, 1, 32), 64>>>(h1, w2, p2, 512, 256, 16);
    reduce_relu4<<<(256 * 512 / 4 + 255) / 256, 256>>>((const float4*)p2, (float4*)h2,
                                                       256 * 512 / 4, 32);

    // L3: 256->128, 8^3->16^3, s2. 32 co-quads, split 16 (4096 warps).
    ct_s2p<8, 2><<<dim3(256, 1, 16), 32>>>(h2, w3, p3, 256, 128, 16);
    reduce_relu4<<<(128 * 4096 / 4 + 255) / 256, 256>>>((const float4*)p3, (float4*)h3,
                                                        128 * 4096 / 4, 16);

    // L4: 128->64, 16^3, s1. 32 co-pairs, split 32 (8192 warps).
    ct_s1p<16, 1><<<dim3(256, 1, 32), 32>>>(h3, w4, p4, 128, 64, 4);
    reduce_relu4<<<(64 * 4096 / 4 + 255) / 256, 256>>>((const float4*)p4, (float4*)h4,
                                                       64 * 4096 / 4, 32);

    // L5: 64->32, 16^3->32^3, s2 scalar, split 8 (8192 warps).
    ct_s2<16><<<dim3(1024, 1, 8), 32>>>(h4, w5, p5, 64, 32, 8);
    reduce_relu4<<<(32 * 32768 / 4 + 255) / 256, 256>>>((const float4*)p5, (float4*)h5,
                                                        32 * 32768 / 4, 8);

    // L6: 32->1, 32^3, s1, no ReLU.
    ct_final<<<256, 128>>>(h5, w6, out);
}